// round 3
// baseline (speedup 1.0000x reference)
#include <cuda_runtime.h>
#include <cstdint>
#include <cstddef>

#define NCH    64
#define OCH    64
#define CONVCH 4096
#define HH     56
#define WW     56
#define PLANE  (HH*WW)     // 3136
#define NPIX   14          // pixels per thread
#define ROWS_HALF 28
#define TROW   30          // tile rows incl. halo
#define TCOL   64          // padded row stride (floats)
#define NREF   128         // 16 mean-groups * 8 max-group
#define NTHR   128
#define NACT   112         // 4 threads/row * 28 rows
#define NJOB   (TROW*14)   // 420 float4 jobs per tile fill

__global__ __launch_bounds__(NTHR)
void prcn_kernel(const float* __restrict__ x,
                 const float* __restrict__ Wt,      // [4096,9]
                 const float* __restrict__ bias,    // [4096]
                 const void*  __restrict__ index_raw, // int32 or int64 [8192]
                 float* __restrict__ out)           // [8,64,56,56]
{
    __shared__ float tile[2][TROW][TCOL];   // double buffer, 15360 B
    __shared__ float wsm[NREF][10];         // 9 weights + bias per ref
    __shared__ int   cidx[NREF];

    const int tid = threadIdx.x;
    const int o   = blockIdx.x & 63;
    const int b   = blockIdx.x >> 6;

    // --- index dtype detection: int32 (JAX x64 off) vs int64 ---
    // Permutation of [0,8192): if stored as int64 LE, every odd int32 word is 0.
    // If int32, words 1,3,5,7 are four distinct perm values -> cannot all be 0.
    const int* idx32 = (const int*)index_raw;
    const bool is64 = ((idx32[1] | idx32[3] | idx32[5] | idx32[7]) == 0);

    if (tid < NREF) {
        int v = is64 ? (int)((const long long*)index_raw)[o*NREF + tid]
                     : idx32[o*NREF + tid];
        cidx[tid] = v & (CONVCH - 1);
    }
    // Zero both buffers once. Fills rewrite cols [4,59] of every row each
    // iteration; halo cols 0..3 / 60..63 stay zero forever.
    for (int j = tid; j < 2*TROW*TCOL; j += NTHR) ((float*)tile)[j] = 0.f;
    __syncthreads();
    for (int j = tid; j < NREF*10; j += NTHR) {
        int k = j / 10, l = j - k*10;
        int c = cidx[k];
        wsm[k][l] = (l < 9) ? Wt[c*9 + l] : bias[c];
    }
    __syncthreads();

    const int tr    = tid >> 2;        // row in half (0..27) for tid < NACT
    const int tx    = tid & 3;
    const int basec = tx*NPIX + 3;     // smem col of plane col (tx*14 - 1)

    for (int half = 0; half < 2; half++) {
        const int r0 = half * ROWS_HALF;

        float4 R[4];
        // Prologue: fetch channel 0 tile into registers
        {
            const int ic = cidx[0] >> 6;
            const float* xp = x + (size_t)(b*NCH + ic) * PLANE;
            #pragma unroll
            for (int m = 0; m < 4; m++) {
                int j = tid + m*NTHR;
                R[m] = make_float4(0.f, 0.f, 0.f, 0.f);
                if (j < NJOB) {
                    int rr = j / 14, cc = (j - rr*14) * 4;
                    int pr = r0 - 1 + rr;
                    if (pr >= 0 && pr < HH)
                        R[m] = *(const float4*)(xp + pr*WW + cc);
                }
            }
        }

        float acc[NPIX], mx[NPIX];
        #pragma unroll
        for (int p = 0; p < NPIX; p++) acc[p] = 0.f;

        for (int k = 0; k < NREF; k++) {
            // Store prefetched registers into tile[k&1]; zeros for halo rows.
            float (*T)[TCOL] = tile[k & 1];
            #pragma unroll
            for (int m = 0; m < 4; m++) {
                int j = tid + m*NTHR;
                if (j < NJOB) {
                    int rr = j / 14, cc = (j - rr*14) * 4;
                    *(float4*)&T[rr][cc + 4] = R[m];
                }
            }
            __syncthreads();   // tile[k&1] ready; everyone left tile[(k-1)&1]

            // Prefetch channel k+1 (LDG latency hides under compute below)
            if (k + 1 < NREF) {
                const int ic = cidx[k+1] >> 6;
                const float* xp = x + (size_t)(b*NCH + ic) * PLANE;
                #pragma unroll
                for (int m = 0; m < 4; m++) {
                    int j = tid + m*NTHR;
                    R[m] = make_float4(0.f, 0.f, 0.f, 0.f);
                    if (j < NJOB) {
                        int rr = j / 14, cc = (j - rr*14) * 4;
                        int pr = r0 - 1 + rr;
                        if (pr >= 0 && pr < HH)
                            R[m] = *(const float4*)(xp + pr*WW + cc);
                    }
                }
            }

            if (tid < NACT) {
                float wv[10];
                #pragma unroll
                for (int l = 0; l < 10; l++) wv[l] = wsm[k][l];

                float s[NPIX];
                #pragma unroll
                for (int p = 0; p < NPIX; p++) s[p] = wv[9];   // bias

                #pragma unroll
                for (int ky = 0; ky < 3; ky++) {
                    const float* rp = &T[tr + ky][basec];
                    float v[NPIX + 2];
                    #pragma unroll
                    for (int i = 0; i < NPIX + 2; i++) v[i] = rp[i];
                    #pragma unroll
                    for (int p = 0; p < NPIX; p++)
                        s[p] += wv[3*ky]*v[p] + wv[3*ky+1]*v[p+1] + wv[3*ky+2]*v[p+2];
                }

                if ((k & 7) == 0) {
                    #pragma unroll
                    for (int p = 0; p < NPIX; p++) mx[p] = s[p];
                } else {
                    #pragma unroll
                    for (int p = 0; p < NPIX; p++) mx[p] = fmaxf(mx[p], s[p]);
                }
                if ((k & 7) == 7) {
                    #pragma unroll
                    for (int p = 0; p < NPIX; p++) acc[p] += mx[p];
                }
            }
        }

        if (tid < NACT) {
            const int h = r0 + tr;
            float* op = out + ((size_t)(b*OCH + o)*HH + h)*WW + tx*NPIX;
            #pragma unroll
            for (int p = 0; p < NPIX; p++) op[p] = acc[p] * 0.0625f;
        }
    }
}

extern "C" void kernel_launch(void* const* d_in, const int* in_sizes, int n_in,
                              void* d_out, int out_size) {
    const float* x    = (const float*)d_in[0];
    const float* Wt   = (const float*)d_in[1];
    const float* bias = (const float*)d_in[2];
    const void*  idx  = (const void*)d_in[3];
    float* out = (float*)d_out;
    prcn_kernel<<<OCH * 8, NTHR>>>(x, Wt, bias, idx, out);
}

// round 4
// speedup vs baseline: 2.0013x; 2.0013x over previous
#include <cuda_runtime.h>
#include <cstdint>
#include <cstddef>

#define NCH    64
#define OCH    64
#define CONVCH 4096
#define HH     56
#define WW     56
#define PLANE  (HH*WW)     // 3136
#define NPIX   14          // pixels per thread
#define ROWS_HALF 28
#define TROW   30          // tile rows incl. halo
#define TCOL   72          // padded row stride (floats). 72 mod 32 = 8 -> rows spread
                           // across bank groups; uniform 2-way conflicts instead of the
                           // 8-way aliasing TCOL=64 (256B stride) produced.
#define NREF   128         // 16 mean-groups * 8 max-group
#define NTHR   128
#define NACT   112         // 4 threads/row * 28 rows
#define NJOB   (TROW*14)   // 420 float4 jobs per tile fill

__global__ __launch_bounds__(NTHR)
void prcn_kernel(const float* __restrict__ x,
                 const float* __restrict__ Wt,      // [4096,9]
                 const float* __restrict__ bias,    // [4096]
                 const void*  __restrict__ index_raw, // int32 or int64 [8192]
                 float* __restrict__ out)           // [8,64,56,56]
{
    __shared__ float tile[2][TROW][TCOL];   // double buffer
    __shared__ float wsm[NREF][10];         // 9 weights + bias per ref
    __shared__ int   cidx[NREF];

    const int tid = threadIdx.x;
    const int o   = blockIdx.x & 63;
    const int b   = blockIdx.x >> 6;

    // --- index dtype detection: int32 (JAX x64 off) vs int64 ---
    // Permutation of [0,8192): if stored as int64 LE, every odd int32 word is 0.
    // If int32, words 1,3,5,7 are four distinct perm values -> cannot all be 0.
    const int* idx32 = (const int*)index_raw;
    const bool is64 = ((idx32[1] | idx32[3] | idx32[5] | idx32[7]) == 0);

    if (tid < NREF) {
        int v = is64 ? (int)((const long long*)index_raw)[o*NREF + tid]
                     : idx32[o*NREF + tid];
        cidx[tid] = v & (CONVCH - 1);
    }
    // Zero both buffers once. Fills rewrite cols [4,59] of every row each
    // iteration; halo cols 0..3 / 60..71 stay zero forever.
    for (int j = tid; j < 2*TROW*TCOL; j += NTHR) ((float*)tile)[j] = 0.f;
    __syncthreads();
    for (int j = tid; j < NREF*10; j += NTHR) {
        int k = j / 10, l = j - k*10;
        int c = cidx[k];
        wsm[k][l] = (l < 9) ? Wt[c*9 + l] : bias[c];
    }
    __syncthreads();

    const int tr    = tid >> 2;        // row in half (0..27) for tid < NACT
    const int tx    = tid & 3;
    const int basec = tx*NPIX + 3;     // smem col of plane col (tx*14 - 1)

    for (int half = 0; half < 2; half++) {
        const int r0 = half * ROWS_HALF;

        float4 R[4];
        // Prologue: fetch channel 0 tile into registers
        {
            const int ic = cidx[0] >> 6;
            const float* xp = x + (size_t)(b*NCH + ic) * PLANE;
            #pragma unroll
            for (int m = 0; m < 4; m++) {
                int j = tid + m*NTHR;
                R[m] = make_float4(0.f, 0.f, 0.f, 0.f);
                if (j < NJOB) {
                    int rr = j / 14, cc = (j - rr*14) * 4;
                    int pr = r0 - 1 + rr;
                    if (pr >= 0 && pr < HH)
                        R[m] = *(const float4*)(xp + pr*WW + cc);
                }
            }
        }

        float acc[NPIX], mx[NPIX];
        #pragma unroll
        for (int p = 0; p < NPIX; p++) acc[p] = 0.f;

        for (int k = 0; k < NREF; k++) {
            // Store prefetched registers into tile[k&1]; zeros for halo rows.
            float (*T)[TCOL] = tile[k & 1];
            #pragma unroll
            for (int m = 0; m < 4; m++) {
                int j = tid + m*NTHR;
                if (j < NJOB) {
                    int rr = j / 14, cc = (j - rr*14) * 4;
                    *(float4*)&T[rr][cc + 4] = R[m];
                }
            }
            __syncthreads();   // tile[k&1] ready; everyone left tile[(k-1)&1]

            // Prefetch channel k+1 (LDG latency hides under compute below)
            if (k + 1 < NREF) {
                const int ic = cidx[k+1] >> 6;
                const float* xp = x + (size_t)(b*NCH + ic) * PLANE;
                #pragma unroll
                for (int m = 0; m < 4; m++) {
                    int j = tid + m*NTHR;
                    R[m] = make_float4(0.f, 0.f, 0.f, 0.f);
                    if (j < NJOB) {
                        int rr = j / 14, cc = (j - rr*14) * 4;
                        int pr = r0 - 1 + rr;
                        if (pr >= 0 && pr < HH)
                            R[m] = *(const float4*)(xp + pr*WW + cc);
                    }
                }
            }

            if (tid < NACT) {
                float wv[10];
                #pragma unroll
                for (int l = 0; l < 10; l++) wv[l] = wsm[k][l];

                float s[NPIX];
                #pragma unroll
                for (int p = 0; p < NPIX; p++) s[p] = wv[9];   // bias

                #pragma unroll
                for (int ky = 0; ky < 3; ky++) {
                    const float* rp = &T[tr + ky][basec];
                    float v[NPIX + 2];
                    #pragma unroll
                    for (int i = 0; i < NPIX + 2; i++) v[i] = rp[i];
                    #pragma unroll
                    for (int p = 0; p < NPIX; p++)
                        s[p] += wv[3*ky]*v[p] + wv[3*ky+1]*v[p+1] + wv[3*ky+2]*v[p+2];
                }

                if ((k & 7) == 0) {
                    #pragma unroll
                    for (int p = 0; p < NPIX; p++) mx[p] = s[p];
                } else {
                    #pragma unroll
                    for (int p = 0; p < NPIX; p++) mx[p] = fmaxf(mx[p], s[p]);
                }
                if ((k & 7) == 7) {
                    #pragma unroll
                    for (int p = 0; p < NPIX; p++) acc[p] += mx[p];
                }
            }
        }

        if (tid < NACT) {
            const int h = r0 + tr;
            float* op = out + ((size_t)(b*OCH + o)*HH + h)*WW + tx*NPIX;
            #pragma unroll
            for (int p = 0; p < NPIX; p++) op[p] = acc[p] * 0.0625f;
        }
    }
}

extern "C" void kernel_launch(void* const* d_in, const int* in_sizes, int n_in,
                              void* d_out, int out_size) {
    const float* x    = (const float*)d_in[0];
    const float* Wt   = (const float*)d_in[1];
    const float* bias = (const float*)d_in[2];
    const void*  idx  = (const void*)d_in[3];
    float* out = (float*)d_out;
    prcn_kernel<<<OCH * 8, NTHR>>>(x, Wt, bias, idx, out);
}